// round 14
// baseline (speedup 1.0000x reference)
#include <cuda_runtime.h>
#include <math.h>

// DGPLoss fused single-kernel: row blocks + fully-async private cp.async
// stages (no barriers in the main loop).
//   seg_feat: [4, 64, 512, 512] fp32   (d_in[0])
//   dep_true: [4, 1, 512, 512]  fp32   (d_in[1])
//   out[0]  : scalar fp32
//
// Block = one image row x batch (2040 blocks, 128 thr, 14 blocks/SM ->
// 98.5% structural slot fill). Per channel each thread cp.asyncs its own
// quad (16B, .cg) and its two patch-center scalars (4B, .ca) into PRIVATE
// smem slots (4 stages, 12.3KB/block). Consumption needs only wait_group 2
// (own-thread visibility) -> zero __syncthreads, warps free-run with 3
// iterations of prefetch slack and zero register cost. Center lines dedup
// in L2 across the 5 row-blocks of each band. Ticket-elected last block
// reduces 2040 partials deterministically.

#define EPSF 1e-8f
#define EPS2 1e-16f
#define CS   262144           // 512*512
#define NH   510
#define NBAT 4
#define NPART (NH * NBAT)     // 2040
#define STAGES 4

typedef unsigned int u32;

__device__ float2 g_part[NPART];
__device__ u32    g_ticket;    // zero-init; reset by last block each run

__device__ __forceinline__ u32 smem_u32(const void* p) {
    return (u32)__cvta_generic_to_shared(p);
}
__device__ __forceinline__ void cp_async16(u32 dst, const float* src) {
    asm volatile("cp.async.cg.shared.global [%0], [%1], 16;\n"
                 :: "r"(dst), "l"(src) : "memory");
}
__device__ __forceinline__ void cp_async4(u32 dst, const float* src) {
    asm volatile("cp.async.ca.shared.global [%0], [%1], 4;\n"
                 :: "r"(dst), "l"(src) : "memory");
}
__device__ __forceinline__ void cp_commit() {
    asm volatile("cp.async.commit_group;\n" ::: "memory");
}
__device__ __forceinline__ void cp_wait2() {
    asm volatile("cp.async.wait_group 2;\n" ::: "memory");
}

__global__ __launch_bounds__(128, 14)
void dgp_fused(const float* __restrict__ seg, const float* __restrict__ dep,
               float* __restrict__ out)
{
    __shared__ float4 s_q[STAGES][128];   // private quad slots
    __shared__ float  s_a[STAGES][128];   // private center-A slots
    __shared__ float  s_b[STAGES][128];   // private center-B slots
    __shared__ float2 sw[4];
    __shared__ bool   isLast;

    const int tid = threadIdx.x;
    const int h   = blockIdx.x;          // 0..509
    const int b   = blockIdx.y;          // 0..3
    const int w0  = tid << 2;            // 0..508

    const int hc  = (h / 5) * 5 + 2;
    const int pA  = w0 / 5;
    const int pB  = (w0 + 3) / 5;        // may be 102 -> reads next-row col (finite, masked)
    const int wcA = pA * 5 + 2;
    const int wcB = pB * 5 + 2;
    const bool sB1 = ((w0 + 1) / 5) != pA;
    const bool sB2 = ((w0 + 2) / 5) != pA;
    const bool sB3 = (pB != pA);

    const int segBase = b * (64 * CS);   // fits int32
    const float* __restrict__ pixp = seg + segBase + h  * 512 + w0;
    const float* __restrict__ ctAp = seg + segBase + hc * 512 + wcA;
    const float* __restrict__ ctBp = seg + segBase + hc * 512 + wcB;

    const u32 qoff = smem_u32(s_q) + (u32)(tid * 16);
    const u32 aoff = smem_u32(s_a) + (u32)(tid * 4);
    const u32 boff = smem_u32(s_b) + (u32)(tid * 4);

    // prologue: stages 0..2 in flight (one group each)
    #pragma unroll
    for (int s = 0; s < 3; ++s) {
        cp_async16(qoff + s * 2048, pixp + s * CS);
        cp_async4 (aoff + s * 512,  ctAp + s * CS);
        cp_async4 (boff + s * 512,  ctBp + s * CS);
        cp_commit();
    }

    float a0 = 0.f, a1 = 0.f, a2 = 0.f, a3 = 0.f;

    #pragma unroll 4
    for (int g = 0; g < 64; ++g) {
        cp_wait2();                       // stage g's group retired

        const int st = g & 3;
        const float4 p  = s_q[st][tid];
        const float  qA = s_a[st][tid];
        const float  qB = s_b[st][tid];

        // issue stage g+3 into slot (g+3)&3 == (g-1)&3 (consumed last iter)
        if (g + 3 < 64) {
            const int sn = (g + 3) & 3;
            cp_async16(qoff + sn * 2048, pixp + (g + 3) * CS);
            cp_async4 (aoff + sn * 512,  ctAp + (g + 3) * CS);
            cp_async4 (boff + sn * 512,  ctBp + (g + 3) * CS);
        }
        cp_commit();                      // empty groups keep counts exact

        const float q1 = sB1 ? qB : qA;
        const float q2 = sB2 ? qB : qA;
        const float q3 = sB3 ? qB : qA;
        float d;
        d = qA - p.x; a0 = fmaf(d, d, a0);
        d = q1 - p.y; a1 = fmaf(d, d, a1);
        d = q2 - p.z; a2 = fmaf(d, d, a2);
        d = q3 - p.w; a3 = fmaf(d, d, a3);
    }

    // ---- depth branch + mask (direct global; tiny) ----
    const int depBase = b * CS;
    const float4 dq  = *(const float4*)(dep + depBase + h * 512 + w0);
    const float  dcA = dep[depBase + hc * 512 + wcA];
    const float  dcB = dep[depBase + hc * 512 + wcB];

    const float dcv[4] = { dcA, sB1 ? dcB : dcA, sB2 ? dcB : dcA, sB3 ? dcB : dcA };
    const int   wcv[4] = { wcA, sB1 ? wcB : wcA, sB2 ? wcB : wcA, sB3 ? wcB : wcA };
    const float av [4] = { a0, a1, a2, a3 };
    const float dpv[4] = { dq.x, dq.y, dq.z, dq.w };

    float sum = 0.f, cnt = 0.f;
    #pragma unroll
    for (int k = 0; k < 4; ++k) {
        const float dd = fabsf(dcv[k] - dpv[k]);
        const bool ic  = (h == hc) && (w0 + k == wcv[k]);
        const bool m   = (dd > EPSF) && (av[k] > EPS2) && (dpv[k] > EPSF) &&
                         !ic && (w0 + k < 510);
        if (m) {
            sum += __expf(-fmaf(dd, 0.1f, av[k]));
            cnt += 1.f;
        }
    }

    // ---- intra-block reduce (4 warps) ----
    #pragma unroll
    for (int o = 16; o > 0; o >>= 1) {
        sum += __shfl_down_sync(0xFFFFFFFFu, sum, o);
        cnt += __shfl_down_sync(0xFFFFFFFFu, cnt, o);
    }
    const int lane = tid & 31;
    const int wid  = tid >> 5;
    if (lane == 0) sw[wid] = make_float2(sum, cnt);
    __syncthreads();

    if (tid == 0) {
        const float2 t0 = sw[0], t1 = sw[1], t2 = sw[2], t3 = sw[3];
        g_part[blockIdx.x + NH * blockIdx.y] =
            make_float2(t0.x + t1.x + t2.x + t3.x, t0.y + t1.y + t2.y + t3.y);
        __threadfence();
        const u32 t = atomicAdd(&g_ticket, 1u);
        isLast = (t == NPART - 1);
    }
    __syncthreads();

    // ---- final deterministic reduction by the last block ----
    if (isLast) {
        __threadfence();
        float s = 0.f, c = 0.f;
        #pragma unroll 4
        for (int i = tid; i < NPART; i += 128) {
            const float2 v = g_part[i];
            s += v.x; c += v.y;
        }
        #pragma unroll
        for (int o = 16; o > 0; o >>= 1) {
            s += __shfl_down_sync(0xFFFFFFFFu, s, o);
            c += __shfl_down_sync(0xFFFFFFFFu, c, o);
        }
        if (lane == 0) sw[wid] = make_float2(s, c);
        __syncthreads();
        if (tid == 0) {
            const float2 t0 = sw[0], t1 = sw[1], t2 = sw[2], t3 = sw[3];
            out[0] = (t0.x + t1.x + t2.x + t3.x) /
                     fmaxf(t0.y + t1.y + t2.y + t3.y, 1.0f);
            g_ticket = 0u;   // reset for next graph replay
        }
    }
}

extern "C" void kernel_launch(void* const* d_in, const int* in_sizes, int n_in,
                              void* d_out, int out_size) {
    const float* seg = (const float*)d_in[0];   // [4,64,512,512]
    const float* dep = (const float*)d_in[1];   // [4,1,512,512]
    float* out = (float*)d_out;

    dim3 grid(NH, NBAT);
    dgp_fused<<<grid, 128>>>(seg, dep, out);
}

// round 15
// speedup vs baseline: 1.3043x; 1.3043x over previous
#include <cuda_runtime.h>
#include <math.h>

// DGPLoss fused single-kernel: band blocks + TMA bulk (cp.async.bulk) stages.
//   seg_feat: [4, 64, 512, 512] fp32   (d_in[0])
//   dep_true: [4, 1, 512, 512]  fp32   (d_in[1])
//   out[0]  : scalar fp32
//
// Block = one 5-row patch band x batch (408 blocks, 640 thr, 3 blocks/SM).
// Per channel the band's 5 rows are one CONTIGUOUS 10KB gmem region:
// thread 0 issues a single cp.async.bulk into a 10KB stage (4 stages, 40KB)
// with mbarrier complete_tx. Consumers: __syncthreads (buffer-reuse safety)
// -> mbarrier parity wait (data prefetched 3 stages ahead -> fast path) ->
// quad LDS.128 + 2 center LDS + 4 FMA. Replaces 160 per-lane LDGSTS per
// stage with ONE bulk op. Ticket-elected last block reduces 408 partials.

#define EPSF 1e-8f
#define EPS2 1e-16f
#define CS   262144              // 512*512
#define NBANDS 102
#define NBAT 4
#define NPART (NBANDS * NBAT)    // 408
#define STAGE_BYTES 10240        // 5*512*4

typedef unsigned int u32;
typedef unsigned long long u64;

__device__ float2 g_part[NPART];
__device__ u32    g_ticket;   // zero-init; reset by last block each run

__device__ __forceinline__ u32 smem_u32(const void* p) {
    return (u32)__cvta_generic_to_shared(p);
}
__device__ __forceinline__ void mbar_init(u32 mbar, u32 count) {
    asm volatile("mbarrier.init.shared.b64 [%0], %1;" :: "r"(mbar), "r"(count) : "memory");
}
__device__ __forceinline__ void mbar_expect_tx(u32 mbar, u32 bytes) {
    asm volatile("mbarrier.arrive.expect_tx.shared.b64 _, [%0], %1;"
                 :: "r"(mbar), "r"(bytes) : "memory");
}
__device__ __forceinline__ void bulk_g2s(u32 dst, const void* src, u32 bytes, u32 mbar) {
    asm volatile("cp.async.bulk.shared::cta.global.mbarrier::complete_tx::bytes "
                 "[%0], [%1], %2, [%3];"
                 :: "r"(dst), "l"(src), "r"(bytes), "r"(mbar) : "memory");
}
__device__ __forceinline__ void mbar_wait(u32 mbar, u32 parity) {
    u32 done;
    asm volatile("{\n\t.reg .pred p;\n\t"
                 "mbarrier.try_wait.parity.acquire.cta.shared::cta.b64 p, [%1], %2;\n\t"
                 "selp.b32 %0, 1, 0, p;\n\t}"
                 : "=r"(done) : "r"(mbar), "r"(parity) : "memory");
    if (!done) {
        asm volatile("{\n\t.reg .pred P1;\n\t"
                     "W_%=:\n\t"
                     "mbarrier.try_wait.parity.acquire.cta.shared::cta.b64 P1, [%0], %1, 0x989680;\n\t"
                     "@P1 bra.uni D_%=;\n\t"
                     "bra.uni W_%=;\n\t"
                     "D_%=:\n\t}"
                     :: "r"(mbar), "r"(parity) : "memory");
    }
}

__global__ __launch_bounds__(640, 3)
void dgp_fused(const float* __restrict__ seg, const float* __restrict__ dep,
               float* __restrict__ out)
{
    __shared__ float sbuf[4][5][512];            // 40 KB stage buffers
    __shared__ __align__(8) u64 mbar_s[4];
    __shared__ float2 s_red[20];
    __shared__ bool   isLast;

    const int tid = threadIdx.x;
    const int r   = tid >> 7;        // row within band: 0..4
    const int wl  = tid & 127;
    const int w0  = wl << 2;         // 0..508
    const int j   = blockIdx.x;      // band 0..101
    const int b   = blockIdx.y;      // batch 0..3
    const int h   = j * 5 + r;
    const int hc  = j * 5 + 2;

    const int pA  = w0 / 5;
    const int pB  = (w0 + 3) / 5;    // may be 102 -> wcB=512 spills into row 3 slot (finite, masked)
    const int wcA = pA * 5 + 2;
    const int wcB = pB * 5 + 2;
    const bool sB1 = ((w0 + 1) / 5) != pA;
    const bool sB2 = ((w0 + 2) / 5) != pA;
    const bool sB3 = (pB != pA);

    const int segBase = b * (64 * CS);   // fits int32
    // band's 5 rows are contiguous: rows 5j..5j+4 = 10KB per channel
    const float* __restrict__ bandSrc = seg + segBase + (j * 5) * 512;

    const u32 sb = smem_u32(sbuf);
    const u32 mb = smem_u32(mbar_s);

    if (tid == 0) {
        #pragma unroll
        for (int s = 0; s < 4; ++s) mbar_init(mb + s * 8, 1);
    }
    __syncthreads();

    // prologue: stages 0..2 in flight
    if (tid == 0) {
        #pragma unroll
        for (int s = 0; s < 3; ++s) {
            mbar_expect_tx(mb + s * 8, STAGE_BYTES);
            bulk_g2s(sb + s * STAGE_BYTES, bandSrc + s * CS, STAGE_BYTES, mb + s * 8);
        }
    }

    float a0 = 0.f, a1 = 0.f, a2 = 0.f, a3 = 0.f;

    #pragma unroll 4
    for (int g = 0; g < 64; ++g) {
        const int st = g & 3;
        const u32 ph = (u32)((g >> 2) & 1);

        __syncthreads();   // all threads done reading buf (g-1)&3 == (g+3)&3

        // producer: issue stage g+3 into the just-freed buffer
        if (tid == 0 && g + 3 < 64) {
            const int sn = (g + 3) & 3;
            mbar_expect_tx(mb + sn * 8, STAGE_BYTES);
            bulk_g2s(sb + sn * STAGE_BYTES, bandSrc + (g + 3) * CS,
                     STAGE_BYTES, mb + sn * 8);
        }

        // consume stage g (usually already landed: 3-stage prefetch)
        mbar_wait(mb + st * 8, ph);

        const float4 p  = *(const float4*)&sbuf[st][r][w0];
        const float  qA = sbuf[st][2][wcA];
        const float  qB = sbuf[st][2][wcB];
        const float  q1 = sB1 ? qB : qA;
        const float  q2 = sB2 ? qB : qA;
        const float  q3 = sB3 ? qB : qA;
        float d;
        d = qA - p.x; a0 = fmaf(d, d, a0);
        d = q1 - p.y; a1 = fmaf(d, d, a1);
        d = q2 - p.z; a2 = fmaf(d, d, a2);
        d = q3 - p.w; a3 = fmaf(d, d, a3);
    }

    // ---- depth branch + mask (direct global; tiny) ----
    const int depBase = b * CS;
    const float4 dq  = *(const float4*)(dep + depBase + h * 512 + w0);
    const float  dcA = dep[depBase + hc * 512 + wcA];
    const float  dcB = dep[depBase + hc * 512 + wcB];

    const float dcv[4] = { dcA, sB1 ? dcB : dcA, sB2 ? dcB : dcA, sB3 ? dcB : dcA };
    const int   wcv[4] = { wcA, sB1 ? wcB : wcA, sB2 ? wcB : wcA, sB3 ? wcB : wcA };
    const float av [4] = { a0, a1, a2, a3 };
    const float dpv[4] = { dq.x, dq.y, dq.z, dq.w };

    float sum = 0.f, cnt = 0.f;
    #pragma unroll
    for (int k = 0; k < 4; ++k) {
        const float dd = fabsf(dcv[k] - dpv[k]);
        const bool ic  = (r == 2) && (w0 + k == wcv[k]);
        const bool m   = (dd > EPSF) && (av[k] > EPS2) && (dpv[k] > EPSF) &&
                         !ic && (w0 + k < 510);
        if (m) {
            sum += __expf(-fmaf(dd, 0.1f, av[k]));
            cnt += 1.f;
        }
    }

    // ---- block reduce (20 warps) ----
    #pragma unroll
    for (int o = 16; o > 0; o >>= 1) {
        sum += __shfl_down_sync(0xFFFFFFFFu, sum, o);
        cnt += __shfl_down_sync(0xFFFFFFFFu, cnt, o);
    }
    const int lane = tid & 31;
    const int wid  = tid >> 5;
    if (lane == 0) s_red[wid] = make_float2(sum, cnt);
    __syncthreads();

    if (wid == 0) {
        float s = (lane < 20) ? s_red[lane].x : 0.f;
        float c = (lane < 20) ? s_red[lane].y : 0.f;
        #pragma unroll
        for (int o = 16; o > 0; o >>= 1) {
            s += __shfl_down_sync(0xFFFFFFFFu, s, o);
            c += __shfl_down_sync(0xFFFFFFFFu, c, o);
        }
        if (lane == 0) {
            g_part[j + NBANDS * b] = make_float2(s, c);
            __threadfence();
            const u32 t = atomicAdd(&g_ticket, 1u);
            isLast = (t == NPART - 1);
        }
    }
    __syncthreads();

    // ---- final deterministic reduction by the last block ----
    if (isLast) {
        __threadfence();
        float s = 0.f, c = 0.f;
        if (tid < NPART) {               // 408 < 640: one partial per thread
            const float2 v = g_part[tid];
            s = v.x; c = v.y;
        }
        #pragma unroll
        for (int o = 16; o > 0; o >>= 1) {
            s += __shfl_down_sync(0xFFFFFFFFu, s, o);
            c += __shfl_down_sync(0xFFFFFFFFu, c, o);
        }
        __syncthreads();                 // s_red reuse
        if (lane == 0) s_red[wid] = make_float2(s, c);
        __syncthreads();
        if (wid == 0) {
            float ts = (lane < 20) ? s_red[lane].x : 0.f;
            float tc = (lane < 20) ? s_red[lane].y : 0.f;
            #pragma unroll
            for (int o = 16; o > 0; o >>= 1) {
                ts += __shfl_down_sync(0xFFFFFFFFu, ts, o);
                tc += __shfl_down_sync(0xFFFFFFFFu, tc, o);
            }
            if (lane == 0) {
                out[0] = ts / fmaxf(tc, 1.0f);
                g_ticket = 0u;           // reset for next graph replay
            }
        }
    }
}

extern "C" void kernel_launch(void* const* d_in, const int* in_sizes, int n_in,
                              void* d_out, int out_size) {
    const float* seg = (const float*)d_in[0];   // [4,64,512,512]
    const float* dep = (const float*)d_in[1];   // [4,1,512,512]
    float* out = (float*)d_out;

    dim3 grid(NBANDS, NBAT);
    dgp_fused<<<grid, 640>>>(seg, dep, out);
}

// round 16
// speedup vs baseline: 1.3087x; 1.0034x over previous
#include <cuda_runtime.h>
#include <math.h>

// DGPLoss fused single-kernel: band blocks + TMA bulk stages with a
// producer/consumer mbarrier pipeline (NO __syncthreads in the main loop).
//   seg_feat: [4, 64, 512, 512] fp32   (d_in[0])
//   dep_true: [4, 1, 512, 512]  fp32   (d_in[1])
//   out[0]  : scalar fp32
//
// Block = one 5-row patch band x batch (408 blocks, 640 thr, 3 blocks/SM).
// 4 x 10KB stages. full[s]: tx mbarrier (count 1) completed by TMA.
// empty[s]: count-20 mbarrier; each warp's lane 0 arrives (after __syncwarp)
// when the warp is done reading stage k -> warps free-run with up to 4 stages
// of skew. Thread 0 waits empty[k&3] (same parity) then bulk-copies stage
// k+4. Ticket-elected last block reduces 408 partials deterministically.

#define EPSF 1e-8f
#define EPS2 1e-16f
#define CS   262144              // 512*512
#define NBANDS 102
#define NBAT 4
#define NPART (NBANDS * NBAT)    // 408
#define STAGE_BYTES 10240        // 5*512*4

typedef unsigned int u32;
typedef unsigned long long u64;

__device__ float2 g_part[NPART];
__device__ u32    g_ticket;   // zero-init; reset by last block each run

__device__ __forceinline__ u32 smem_u32(const void* p) {
    return (u32)__cvta_generic_to_shared(p);
}
__device__ __forceinline__ void mbar_init(u32 mbar, u32 count) {
    asm volatile("mbarrier.init.shared.b64 [%0], %1;" :: "r"(mbar), "r"(count) : "memory");
}
__device__ __forceinline__ void mbar_arrive(u32 mbar) {
    asm volatile("mbarrier.arrive.release.cta.shared::cta.b64 _, [%0];"
                 :: "r"(mbar) : "memory");
}
__device__ __forceinline__ void mbar_expect_tx(u32 mbar, u32 bytes) {
    asm volatile("mbarrier.arrive.expect_tx.shared.b64 _, [%0], %1;"
                 :: "r"(mbar), "r"(bytes) : "memory");
}
__device__ __forceinline__ void bulk_g2s(u32 dst, const void* src, u32 bytes, u32 mbar) {
    asm volatile("cp.async.bulk.shared::cta.global.mbarrier::complete_tx::bytes "
                 "[%0], [%1], %2, [%3];"
                 :: "r"(dst), "l"(src), "r"(bytes), "r"(mbar) : "memory");
}
__device__ __forceinline__ void mbar_wait(u32 mbar, u32 parity) {
    u32 done;
    asm volatile("{\n\t.reg .pred p;\n\t"
                 "mbarrier.try_wait.parity.acquire.cta.shared::cta.b64 p, [%1], %2;\n\t"
                 "selp.b32 %0, 1, 0, p;\n\t}"
                 : "=r"(done) : "r"(mbar), "r"(parity) : "memory");
    if (!done) {
        asm volatile("{\n\t.reg .pred P1;\n\t"
                     "W_%=:\n\t"
                     "mbarrier.try_wait.parity.acquire.cta.shared::cta.b64 P1, [%0], %1, 0x989680;\n\t"
                     "@P1 bra.uni D_%=;\n\t"
                     "bra.uni W_%=;\n\t"
                     "D_%=:\n\t}"
                     :: "r"(mbar), "r"(parity) : "memory");
    }
}

__global__ __launch_bounds__(640, 3)
void dgp_fused(const float* __restrict__ seg, const float* __restrict__ dep,
               float* __restrict__ out)
{
    __shared__ float sbuf[4][5][512];            // 40 KB stage buffers
    __shared__ __align__(8) u64 full_b[4];
    __shared__ __align__(8) u64 empty_b[4];
    __shared__ float2 s_red[20];
    __shared__ bool   isLast;

    const int tid = threadIdx.x;
    const int r   = tid >> 7;        // row within band: 0..4
    const int wl  = tid & 127;
    const int w0  = wl << 2;         // 0..508
    const int j   = blockIdx.x;      // band 0..101
    const int b   = blockIdx.y;      // batch 0..3
    const int h   = j * 5 + r;
    const int hc  = j * 5 + 2;

    const int pA  = w0 / 5;
    const int pB  = (w0 + 3) / 5;    // may be 102 -> wcB=512 spills into row-3 slot (finite, masked)
    const int wcA = pA * 5 + 2;
    const int wcB = pB * 5 + 2;
    const bool sB1 = ((w0 + 1) / 5) != pA;
    const bool sB2 = ((w0 + 2) / 5) != pA;
    const bool sB3 = (pB != pA);

    const int segBase = b * (64 * CS);   // fits int32
    const float* __restrict__ bandSrc = seg + segBase + (j * 5) * 512;

    const u32 sb = smem_u32(sbuf);
    const u32 fb = smem_u32(full_b);
    const u32 eb = smem_u32(empty_b);

    if (tid == 0) {
        #pragma unroll
        for (int s = 0; s < 4; ++s) {
            mbar_init(fb + s * 8, 1);    // completed by TMA tx
            mbar_init(eb + s * 8, 20);   // one arrive per warp
        }
    }
    __syncthreads();

    // prologue: stages 0..3 in flight
    if (tid == 0) {
        #pragma unroll
        for (int s = 0; s < 4; ++s) {
            mbar_expect_tx(fb + s * 8, STAGE_BYTES);
            bulk_g2s(sb + s * STAGE_BYTES, bandSrc + s * CS, STAGE_BYTES, fb + s * 8);
        }
    }

    float a0 = 0.f, a1 = 0.f, a2 = 0.f, a3 = 0.f;
    const int lane = tid & 31;

    #pragma unroll 4
    for (int k = 0; k < 64; ++k) {
        const int st = k & 3;
        const u32 ph = (u32)((k >> 2) & 1);

        // consume stage k (3-4 stages of prefetch slack -> usually fast path)
        mbar_wait(fb + st * 8, ph);

        const float4 p  = *(const float4*)&sbuf[st][r][w0];
        const float  qA = sbuf[st][2][wcA];
        const float  qB = sbuf[st][2][wcB];

        // release the buffer: one elected arrive per warp
        __syncwarp();
        if (lane == 0) mbar_arrive(eb + st * 8);

        // producer: once all 20 warps released buf st, refill with stage k+4
        if (tid == 0 && k < 60) {
            mbar_wait(eb + st * 8, ph);
            mbar_expect_tx(fb + st * 8, STAGE_BYTES);
            bulk_g2s(sb + st * STAGE_BYTES, bandSrc + (k + 4) * CS,
                     STAGE_BYTES, fb + st * 8);
        }

        const float q1 = sB1 ? qB : qA;
        const float q2 = sB2 ? qB : qA;
        const float q3 = sB3 ? qB : qA;
        float d;
        d = qA - p.x; a0 = fmaf(d, d, a0);
        d = q1 - p.y; a1 = fmaf(d, d, a1);
        d = q2 - p.z; a2 = fmaf(d, d, a2);
        d = q3 - p.w; a3 = fmaf(d, d, a3);
    }

    // ---- depth branch + mask (direct global; tiny) ----
    const int depBase = b * CS;
    const float4 dq  = *(const float4*)(dep + depBase + h * 512 + w0);
    const float  dcA = dep[depBase + hc * 512 + wcA];
    const float  dcB = dep[depBase + hc * 512 + wcB];

    const float dcv[4] = { dcA, sB1 ? dcB : dcA, sB2 ? dcB : dcA, sB3 ? dcB : dcA };
    const int   wcv[4] = { wcA, sB1 ? wcB : wcA, sB2 ? wcB : wcA, sB3 ? wcB : wcA };
    const float av [4] = { a0, a1, a2, a3 };
    const float dpv[4] = { dq.x, dq.y, dq.z, dq.w };

    float sum = 0.f, cnt = 0.f;
    #pragma unroll
    for (int k = 0; k < 4; ++k) {
        const float dd = fabsf(dcv[k] - dpv[k]);
        const bool ic  = (r == 2) && (w0 + k == wcv[k]);
        const bool m   = (dd > EPSF) && (av[k] > EPS2) && (dpv[k] > EPSF) &&
                         !ic && (w0 + k < 510);
        if (m) {
            sum += __expf(-fmaf(dd, 0.1f, av[k]));
            cnt += 1.f;
        }
    }

    // ---- block reduce (20 warps) ----
    #pragma unroll
    for (int o = 16; o > 0; o >>= 1) {
        sum += __shfl_down_sync(0xFFFFFFFFu, sum, o);
        cnt += __shfl_down_sync(0xFFFFFFFFu, cnt, o);
    }
    const int wid = tid >> 5;
    if (lane == 0) s_red[wid] = make_float2(sum, cnt);
    __syncthreads();

    if (wid == 0) {
        float s = (lane < 20) ? s_red[lane].x : 0.f;
        float c = (lane < 20) ? s_red[lane].y : 0.f;
        #pragma unroll
        for (int o = 16; o > 0; o >>= 1) {
            s += __shfl_down_sync(0xFFFFFFFFu, s, o);
            c += __shfl_down_sync(0xFFFFFFFFu, c, o);
        }
        if (lane == 0) {
            g_part[j + NBANDS * b] = make_float2(s, c);
            __threadfence();
            const u32 t = atomicAdd(&g_ticket, 1u);
            isLast = (t == NPART - 1);
        }
    }
    __syncthreads();

    // ---- final deterministic reduction by the last block ----
    if (isLast) {
        __threadfence();
        float s = 0.f, c = 0.f;
        if (tid < NPART) {               // 408 < 640: one partial per thread
            const float2 v = g_part[tid];
            s = v.x; c = v.y;
        }
        #pragma unroll
        for (int o = 16; o > 0; o >>= 1) {
            s += __shfl_down_sync(0xFFFFFFFFu, s, o);
            c += __shfl_down_sync(0xFFFFFFFFu, c, o);
        }
        __syncthreads();                 // s_red reuse
        if (lane == 0) s_red[wid] = make_float2(s, c);
        __syncthreads();
        if (wid == 0) {
            float ts = (lane < 20) ? s_red[lane].x : 0.f;
            float tc = (lane < 20) ? s_red[lane].y : 0.f;
            #pragma unroll
            for (int o = 16; o > 0; o >>= 1) {
                ts += __shfl_down_sync(0xFFFFFFFFu, ts, o);
                tc += __shfl_down_sync(0xFFFFFFFFu, tc, o);
            }
            if (lane == 0) {
                out[0] = ts / fmaxf(tc, 1.0f);
                g_ticket = 0u;           // reset for next graph replay
            }
        }
    }
}

extern "C" void kernel_launch(void* const* d_in, const int* in_sizes, int n_in,
                              void* d_out, int out_size) {
    const float* seg = (const float*)d_in[0];   // [4,64,512,512]
    const float* dep = (const float*)d_in[1];   // [4,1,512,512]
    float* out = (float*)d_out;

    dim3 grid(NBANDS, NBAT);
    dgp_fused<<<grid, 640>>>(seg, dep, out);
}

// round 17
// speedup vs baseline: 1.3546x; 1.0351x over previous
#include <cuda_runtime.h>
#include <math.h>

// DGPLoss fused single-kernel: band blocks + 4-stage cp.async smem pipeline.
//   seg_feat: [4, 64, 512, 512] fp32   (d_in[0])
//   dep_true: [4, 1, 512, 512]  fp32   (d_in[1])
//   out[0]  : scalar fp32
//
// FINAL (R11 variant, best bench 45.6us, ~98% of the empirical ~6.0 TB/s
// streaming ceiling for this pattern on GB300):
// Block = one 5-row patch band x batch (408 blocks, 640 thr, 3 blocks/SM).
// Per channel: each thread cp.async's its 16B quad into a 10KB stage buffer
// (4 stages, 40KB). Channel g's data is requested 3 iterations before use,
// decoupling DRAM latency from the compute chain at zero register cost.
// Quads AND patch centers are read from the same smem tile (center row =
// band row 2). One wait_group + one __syncthreads per channel. Ticket-
// elected last block reduces 408 partials deterministically.

#define EPSF 1e-8f
#define EPS2 1e-16f
#define CS   262144              // 512*512
#define NBANDS 102
#define NBAT 4
#define NPART (NBANDS * NBAT)    // 408
#define STAGES 4
#define STAGE_BYTES (5 * 512 * 4)   // 10240

typedef unsigned int u32;

__device__ float2 g_part[NPART];
__device__ u32    g_ticket;   // zero-init; reset by last block each run

__device__ __forceinline__ u32 smem_u32(const void* p) {
    return (u32)__cvta_generic_to_shared(p);
}
__device__ __forceinline__ void cp_async16(u32 dst, const float* src) {
    asm volatile("cp.async.cg.shared.global [%0], [%1], 16;\n"
                 :: "r"(dst), "l"(src) : "memory");
}
__device__ __forceinline__ void cp_commit() {
    asm volatile("cp.async.commit_group;\n" ::: "memory");
}
__device__ __forceinline__ void cp_wait2() {
    asm volatile("cp.async.wait_group 2;\n" ::: "memory");
}

__global__ __launch_bounds__(640, 3)
void dgp_fused(const float* __restrict__ seg, const float* __restrict__ dep,
               float* __restrict__ out)
{
    __shared__ float  sbuf[STAGES][5][512];   // 40 KB
    __shared__ float2 s_red[20];
    __shared__ bool   isLast;

    const int tid = threadIdx.x;
    const int r   = tid >> 7;        // row within band: 0..4
    const int wl  = tid & 127;
    const int w0  = wl << 2;         // 0..508
    const int j   = blockIdx.x;      // band 0..101
    const int b   = blockIdx.y;      // batch 0..3
    const int h   = j * 5 + r;
    const int hc  = j * 5 + 2;

    const int pA  = w0 / 5;
    const int pB  = (w0 + 3) / 5;    // may be 102 -> wcB=512 reads row3 col0 (finite, masked)
    const int wcA = pA * 5 + 2;
    const int wcB = pB * 5 + 2;
    const bool sB1 = ((w0 + 1) / 5) != pA;
    const bool sB2 = ((w0 + 2) / 5) != pA;
    const bool sB3 = (pB != pA);

    const int segBase = b * (64 * CS);   // fits int32
    const float* __restrict__ src0 = seg + segBase + h * 512 + w0;

    const u32 sb     = smem_u32(sbuf);
    const u32 dstoff = (u32)((r * 512 + w0) * 4);

    // prologue: stages 0..2 in flight
    #pragma unroll
    for (int s = 0; s < 3; ++s) {
        cp_async16(sb + s * STAGE_BYTES + dstoff, src0 + s * CS);
        cp_commit();
    }

    float a0 = 0.f, a1 = 0.f, a2 = 0.f, a3 = 0.f;

    #pragma unroll 4
    for (int g = 0; g < 64; ++g) {
        cp_wait2();          // stage g arrived (this thread's copies)
        __syncthreads();     // stage g visible from ALL threads

        // issue stage g+3 into buf (g+3)&3 == (g-1)&3 (fully consumed pre-BAR)
        if (g + 3 < 64)
            cp_async16(sb + ((g + 3) & 3) * STAGE_BYTES + dstoff,
                       src0 + (g + 3) * CS);
        cp_commit();         // commit every iter (empty groups keep counts exact)

        const int st = g & 3;
        const float4 p  = *(const float4*)&sbuf[st][r][w0];
        const float  qA = sbuf[st][2][wcA];
        const float  qB = sbuf[st][2][wcB];
        const float  q1 = sB1 ? qB : qA;
        const float  q2 = sB2 ? qB : qA;
        const float  q3 = sB3 ? qB : qA;
        float d;
        d = qA - p.x; a0 = fmaf(d, d, a0);
        d = q1 - p.y; a1 = fmaf(d, d, a1);
        d = q2 - p.z; a2 = fmaf(d, d, a2);
        d = q3 - p.w; a3 = fmaf(d, d, a3);
    }

    // ---- depth branch + mask (direct global; tiny) ----
    const int depBase = b * CS;
    const float4 dq  = *(const float4*)(dep + depBase + h * 512 + w0);
    const float  dcA = dep[depBase + hc * 512 + wcA];
    const float  dcB = dep[depBase + hc * 512 + wcB];

    const float dcv[4] = { dcA, sB1 ? dcB : dcA, sB2 ? dcB : dcA, sB3 ? dcB : dcA };
    const int   wcv[4] = { wcA, sB1 ? wcB : wcA, sB2 ? wcB : wcA, sB3 ? wcB : wcA };
    const float av [4] = { a0, a1, a2, a3 };
    const float dpv[4] = { dq.x, dq.y, dq.z, dq.w };

    float sum = 0.f, cnt = 0.f;
    #pragma unroll
    for (int k = 0; k < 4; ++k) {
        const float dd = fabsf(dcv[k] - dpv[k]);
        const bool ic  = (r == 2) && (w0 + k == wcv[k]);
        const bool m   = (dd > EPSF) && (av[k] > EPS2) && (dpv[k] > EPSF) &&
                         !ic && (w0 + k < 510);
        if (m) {
            sum += __expf(-fmaf(dd, 0.1f, av[k]));
            cnt += 1.f;
        }
    }

    // ---- block reduce (20 warps) ----
    #pragma unroll
    for (int o = 16; o > 0; o >>= 1) {
        sum += __shfl_down_sync(0xFFFFFFFFu, sum, o);
        cnt += __shfl_down_sync(0xFFFFFFFFu, cnt, o);
    }
    const int lane = tid & 31;
    const int wid  = tid >> 5;
    if (lane == 0) s_red[wid] = make_float2(sum, cnt);
    __syncthreads();

    if (wid == 0) {
        float s = (lane < 20) ? s_red[lane].x : 0.f;
        float c = (lane < 20) ? s_red[lane].y : 0.f;
        #pragma unroll
        for (int o = 16; o > 0; o >>= 1) {
            s += __shfl_down_sync(0xFFFFFFFFu, s, o);
            c += __shfl_down_sync(0xFFFFFFFFu, c, o);
        }
        if (lane == 0) {
            g_part[j + NBANDS * b] = make_float2(s, c);
            __threadfence();
            const u32 t = atomicAdd(&g_ticket, 1u);
            isLast = (t == NPART - 1);
        }
    }
    __syncthreads();

    // ---- final deterministic reduction by the last block ----
    if (isLast) {
        __threadfence();
        float s = 0.f, c = 0.f;
        if (tid < NPART) {               // 408 < 640: one partial per thread
            const float2 v = g_part[tid];
            s = v.x; c = v.y;
        }
        #pragma unroll
        for (int o = 16; o > 0; o >>= 1) {
            s += __shfl_down_sync(0xFFFFFFFFu, s, o);
            c += __shfl_down_sync(0xFFFFFFFFu, c, o);
        }
        __syncthreads();                 // s_red reuse
        if (lane == 0) s_red[wid] = make_float2(s, c);
        __syncthreads();
        if (wid == 0) {
            float ts = (lane < 20) ? s_red[lane].x : 0.f;
            float tc = (lane < 20) ? s_red[lane].y : 0.f;
            #pragma unroll
            for (int o = 16; o > 0; o >>= 1) {
                ts += __shfl_down_sync(0xFFFFFFFFu, ts, o);
                tc += __shfl_down_sync(0xFFFFFFFFu, tc, o);
            }
            if (lane == 0) {
                out[0] = ts / fmaxf(tc, 1.0f);
                g_ticket = 0u;           // reset for next graph replay
            }
        }
    }
}

extern "C" void kernel_launch(void* const* d_in, const int* in_sizes, int n_in,
                              void* d_out, int out_size) {
    const float* seg = (const float*)d_in[0];   // [4,64,512,512]
    const float* dep = (const float*)d_in[1];   // [4,1,512,512]
    float* out = (float*)d_out;

    dim3 grid(NBANDS, NBAT);
    dgp_fused<<<grid, 640>>>(seg, dep, out);
}